// round 16
// baseline (speedup 1.0000x reference)
#include <cuda_runtime.h>
#include <cuda_bf16.h>
#include <cstdint>

#define N_NODES 50000
#define N_EDGES 500000
#define DIM     512
#define NCLS    100

// ---------------------------------------------------------------------------
// scratch (device globals)
// ---------------------------------------------------------------------------
__device__ float g_h  [(size_t)N_NODES * DIM];
__device__ float g_agg[(size_t)N_NODES * DIM];
__device__ float g_norm[N_NODES];
__device__ int   g_cnt [N_NODES];
__device__ int   g_fill[N_NODES];
__device__ int   g_off [N_NODES + 1];
__device__ int2  g_csr [N_EDGES];     // packed (src, coef-as-bits)

__device__ __nv_bfloat16 g_w1hi[(size_t)DIM * DIM];
__device__ __nv_bfloat16 g_w1lo[(size_t)DIM * DIM];
__device__ __nv_bfloat16 g_w2hi[(size_t)DIM * DIM];
__device__ __nv_bfloat16 g_w2lo[(size_t)DIM * DIM];
__device__ __nv_bfloat16 g_wchi[(size_t)NCLS * DIM];
__device__ __nv_bfloat16 g_wclo[(size_t)NCLS * DIM];

#define SCAN_BLOCKS 196
__device__ int g_bsum[SCAN_BLOCKS];
__device__ int g_bpre[SCAN_BLOCKS];

// ---------------------------------------------------------------------------
// CSR build
// ---------------------------------------------------------------------------
__global__ void k_zero_cnt() {
    int i = blockIdx.x * blockDim.x + threadIdx.x;
    if (i < N_NODES) { g_cnt[i] = 0; g_fill[i] = 0; }
}

__global__ void k_count(const int* __restrict__ ei) {
    int e = blockIdx.x * blockDim.x + threadIdx.x;
    if (e < N_EDGES) atomicAdd(&g_cnt[ei[N_EDGES + e]], 1);
}

__global__ void k_norm() {
    int i = blockIdx.x * blockDim.x + threadIdx.x;
    if (i < N_NODES) g_norm[i] = rsqrtf(1.0f + (float)g_cnt[i]);
}

__device__ __forceinline__ int block_scan256(int v, int t, int* sh, int* tot) {
    int incl = v;
#pragma unroll
    for (int o = 1; o < 32; o <<= 1) {
        int u = __shfl_up_sync(0xffffffffu, incl, o);
        if ((t & 31) >= o) incl += u;
    }
    if ((t & 31) == 31) sh[t >> 5] = incl;
    __syncthreads();
    if (t < 8) {
        int w = sh[t];
        int iw = w;
#pragma unroll
        for (int o = 1; o < 8; o <<= 1) {
            int u = __shfl_up_sync(0xffu, iw, o);
            if (t >= o) iw += u;
        }
        sh[t] = iw - w;
        if (t == 7) *tot = iw;
    }
    __syncthreads();
    return incl + sh[t >> 5];
}

__global__ void __launch_bounds__(256) k_scan1() {
    __shared__ int sh[8]; __shared__ int tot;
    int i = blockIdx.x * 256 + threadIdx.x;
    int v = (i < N_NODES) ? g_cnt[i] : 0;
    block_scan256(v, threadIdx.x, sh, &tot);
    __syncthreads();
    if (threadIdx.x == 0) g_bsum[blockIdx.x] = tot;
}

__global__ void __launch_bounds__(256) k_scan2() {
    __shared__ int sh[8]; __shared__ int tot;
    int t = threadIdx.x;
    int v = (t < SCAN_BLOCKS) ? g_bsum[t] : 0;
    int incl = block_scan256(v, t, sh, &tot);
    if (t < SCAN_BLOCKS) g_bpre[t] = incl - v;
}

__global__ void __launch_bounds__(256) k_scan3() {
    __shared__ int sh[8]; __shared__ int tot;
    int i = blockIdx.x * 256 + threadIdx.x;
    int v = (i < N_NODES) ? g_cnt[i] : 0;
    int incl = block_scan256(v, threadIdx.x, sh, &tot);
    if (i < N_NODES) g_off[i + 1] = incl + g_bpre[blockIdx.x];
    if (i == 0) g_off[0] = 0;
}

__global__ void k_fill(const int* __restrict__ ei) {
    int e = blockIdx.x * blockDim.x + threadIdx.x;
    if (e >= N_EDGES) return;
    int src = ei[e];
    int dst = ei[N_EDGES + e];
    int pos = g_off[dst] + atomicAdd(&g_fill[dst], 1);
    float coef = g_norm[src] * g_norm[dst];
    g_csr[pos] = make_int2(src, __float_as_int(coef));
}

// ---------------------------------------------------------------------------
// fp32 -> (hi, lo) bf16 split
// ---------------------------------------------------------------------------
__device__ __forceinline__ void split2(float2 a, unsigned& hi2, unsigned& lo2) {
    __nv_bfloat16 hx = __float2bfloat16(a.x);
    __nv_bfloat16 hy = __float2bfloat16(a.y);
    __nv_bfloat16 lx = __float2bfloat16(a.x - __bfloat162float(hx));
    __nv_bfloat16 ly = __float2bfloat16(a.y - __bfloat162float(hy));
    __nv_bfloat162 h = __halves2bfloat162(hx, hy);
    __nv_bfloat162 l = __halves2bfloat162(lx, ly);
    hi2 = *reinterpret_cast<unsigned*>(&h);
    lo2 = *reinterpret_cast<unsigned*>(&l);
}

__global__ void k_split_w(const float* __restrict__ src,
                          __nv_bfloat16* __restrict__ whi,
                          __nv_bfloat16* __restrict__ wlo, int n) {
    int i2 = blockIdx.x * blockDim.x + threadIdx.x;
    int total2 = n * (DIM / 2);
    if (i2 >= total2) return;
    float2 a = reinterpret_cast<const float2*>(src)[i2];
    unsigned hi2, lo2;
    split2(a, hi2, lo2);
    reinterpret_cast<unsigned*>(whi)[i2] = hi2;
    reinterpret_cast<unsigned*>(wlo)[i2] = lo2;
}

// ---------------------------------------------------------------------------
// gather aggregation (fused self-loop + bias + relu)
// feature-tiled via blockIdx.y: columns [y*256, y*256+256); 64 threads/block
// unroll-8 edge loop; packed (src,coef) int2 loads
// ---------------------------------------------------------------------------
__global__ void __launch_bounds__(64) k_gather(const float* __restrict__ h,
                                               float* __restrict__ agg,
                                               const float* __restrict__ bias) {
    const int node   = blockIdx.x;
    const int colOff = blockIdx.y * 256;
    const int t      = threadIdx.x;
    const int beg    = g_off[node];
    const int end    = g_off[node + 1];
    const float* hc  = h + colOff;

    float4 acc = make_float4(0.f, 0.f, 0.f, 0.f);

    int p = beg;
    for (; p + 8 <= end; p += 8) {
        int2 sc[8];
#pragma unroll
        for (int q = 0; q < 8; q++) sc[q] = __ldg(&g_csr[p + q]);
        float4 v[8];
#pragma unroll
        for (int q = 0; q < 8; q++)
            v[q] = reinterpret_cast<const float4*>(hc + (size_t)sc[q].x * DIM)[t];
#pragma unroll
        for (int q = 0; q < 8; q++) {
            float c = __int_as_float(sc[q].y);
            acc.x = fmaf(c, v[q].x, acc.x); acc.y = fmaf(c, v[q].y, acc.y);
            acc.z = fmaf(c, v[q].z, acc.z); acc.w = fmaf(c, v[q].w, acc.w);
        }
    }
    for (; p + 4 <= end; p += 4) {
        int2 sc0 = __ldg(&g_csr[p]),     sc1 = __ldg(&g_csr[p + 1]);
        int2 sc2 = __ldg(&g_csr[p + 2]), sc3 = __ldg(&g_csr[p + 3]);
        float4 v0 = reinterpret_cast<const float4*>(hc + (size_t)sc0.x * DIM)[t];
        float4 v1 = reinterpret_cast<const float4*>(hc + (size_t)sc1.x * DIM)[t];
        float4 v2 = reinterpret_cast<const float4*>(hc + (size_t)sc2.x * DIM)[t];
        float4 v3 = reinterpret_cast<const float4*>(hc + (size_t)sc3.x * DIM)[t];
        float c0 = __int_as_float(sc0.y), c1 = __int_as_float(sc1.y);
        float c2 = __int_as_float(sc2.y), c3 = __int_as_float(sc3.y);
        acc.x = fmaf(c0, v0.x, acc.x); acc.y = fmaf(c0, v0.y, acc.y);
        acc.z = fmaf(c0, v0.z, acc.z); acc.w = fmaf(c0, v0.w, acc.w);
        acc.x = fmaf(c1, v1.x, acc.x); acc.y = fmaf(c1, v1.y, acc.y);
        acc.z = fmaf(c1, v1.z, acc.z); acc.w = fmaf(c1, v1.w, acc.w);
        acc.x = fmaf(c2, v2.x, acc.x); acc.y = fmaf(c2, v2.y, acc.y);
        acc.z = fmaf(c2, v2.z, acc.z); acc.w = fmaf(c2, v2.w, acc.w);
        acc.x = fmaf(c3, v3.x, acc.x); acc.y = fmaf(c3, v3.y, acc.y);
        acc.z = fmaf(c3, v3.z, acc.z); acc.w = fmaf(c3, v3.w, acc.w);
    }
    for (; p < end; p++) {
        int2 sc = __ldg(&g_csr[p]);
        float c = __int_as_float(sc.y);
        float4 v = reinterpret_cast<const float4*>(hc + (size_t)sc.x * DIM)[t];
        acc.x = fmaf(c, v.x, acc.x);
        acc.y = fmaf(c, v.y, acc.y);
        acc.z = fmaf(c, v.z, acc.z);
        acc.w = fmaf(c, v.w, acc.w);
    }

    float cs = g_norm[node];
    cs = cs * cs;
    float4 hv = reinterpret_cast<const float4*>(hc + (size_t)node * DIM)[t];
    float4 b  = reinterpret_cast<const float4*>(bias + colOff)[t];
    float4 r;
    r.x = fmaxf(fmaf(cs, hv.x, acc.x) + b.x, 0.f);
    r.y = fmaxf(fmaf(cs, hv.y, acc.y) + b.y, 0.f);
    r.z = fmaxf(fmaf(cs, hv.z, acc.z) + b.z, 0.f);
    r.w = fmaxf(fmaf(cs, hv.w, acc.w) + b.w, 0.f);
    reinterpret_cast<float4*>(agg + (size_t)node * DIM + colOff)[t] = r;
}

// ---------------------------------------------------------------------------
// pipelined fused split + bf16 mma.sync GEMM (2-stage, XOR-toggle — verified)
// block 128x128, K-chunk 32, 256 threads = 8 warps as 2(M) x 4(N)
// ---------------------------------------------------------------------------
#define GBM 128
#define GBN 128
#define GBK 32
#define APITCH 40
#define SEC    10240
#define STAGEB (4 * SEC)
#define SMEMB  (2 * STAGEB)

__device__ __forceinline__ void mma_bf16(float* d, const unsigned* a,
                                         unsigned b0, unsigned b1) {
    asm volatile(
        "mma.sync.aligned.m16n8k16.row.col.f32.bf16.bf16.f32 "
        "{%0,%1,%2,%3}, {%4,%5,%6,%7}, {%8,%9}, {%0,%1,%2,%3};"
        : "+f"(d[0]), "+f"(d[1]), "+f"(d[2]), "+f"(d[3])
        : "r"(a[0]), "r"(a[1]), "r"(a[2]), "r"(a[3]), "r"(b0), "r"(b1));
}

__device__ __forceinline__ void ldmx4(unsigned* r, unsigned addr) {
    asm volatile(
        "ldmatrix.sync.aligned.m8n8.x4.shared.b16 {%0,%1,%2,%3}, [%4];"
        : "=r"(r[0]), "=r"(r[1]), "=r"(r[2]), "=r"(r[3])
        : "r"(addr));
}

__device__ __forceinline__ void cp_async16(uint32_t dst, const void* src) {
    asm volatile("cp.async.cg.shared.global [%0], [%1], 16;" :: "r"(dst), "l"(src) : "memory");
}
#define CP_COMMIT() asm volatile("cp.async.commit_group;" ::: "memory")
#define CP_WAIT0()  asm volatile("cp.async.wait_group 0;"  ::: "memory")

__global__ void __launch_bounds__(256) k_gemm_fused(const float* __restrict__ A,
                                                    const __nv_bfloat16* __restrict__ Whi,
                                                    const __nv_bfloat16* __restrict__ Wlo,
                                                    float* __restrict__ C,
                                                    const float* __restrict__ bias,
                                                    int N, int M) {
    extern __shared__ char smem[];
    uint32_t sb;
    asm("{ .reg .u64 t; cvta.to.shared.u64 t, %1; cvt.u32.u64 %0, t; }" : "=r"(sb) : "l"(smem));

    const int t    = threadIdx.x;
    const int lane = t & 31;
    const int warp = t >> 5;
    const int wm   = warp & 1;
    const int wn   = warp >> 1;
    const int rowBase = blockIdx.y * GBM;
    const int colBase = blockIdx.x * GBN;

    const int lg = lane >> 3;
    const int lr = lane & 7;

#pragma unroll
    for (int i = 0; i < SMEMB / 16 / 256; i++)
        reinterpret_cast<uint4*>(smem)[i * 256 + t] = make_uint4(0, 0, 0, 0);
    __syncthreads();

    float acc[4][4][4];
#pragma unroll
    for (int i = 0; i < 4; i++)
#pragma unroll
        for (int j = 0; j < 4; j++)
#pragma unroll
            for (int q = 0; q < 4; q++) acc[i][j][q] = 0.f;

    // ---- prologue: stage 0 ----
    {
        const int k0 = 0;
        float4 aPre[4];
#pragma unroll
        for (int L = 0; L < 4; L++) {
            int chunk = t + L * 256;
            int r = chunk >> 3, c = chunk & 7;
            int gr = rowBase + r;
            if (gr < N) aPre[L] = *reinterpret_cast<const float4*>(A + (size_t)gr * DIM + k0 + c * 4);
        }
#pragma unroll
        for (int L = 0; L < 2; L++) {
            int chunk = t + L * 256;
            int r = chunk >> 2, c = chunk & 3;
            int gc = colBase + r;
            if (gc < M) {
                uint32_t off = (uint32_t)((r * APITCH + c * 8) * 2);
                cp_async16(sb + 2 * SEC + off, Whi + (size_t)gc * DIM + k0 + c * 8);
                cp_async16(sb + 3 * SEC + off, Wlo + (size_t)gc * DIM + k0 + c * 8);
            }
        }
        CP_COMMIT();
#pragma unroll
        for (int L = 0; L < 4; L++) {
            int chunk = t + L * 256;
            int r = chunk >> 3, c = chunk & 7;
            int gr = rowBase + r;
            if (gr < N) {
                unsigned h0, l0, h1, l1;
                split2(make_float2(aPre[L].x, aPre[L].y), h0, l0);
                split2(make_float2(aPre[L].z, aPre[L].w), h1, l1);
                uint32_t off = (uint32_t)((r * APITCH + c * 4) * 2);
                *reinterpret_cast<uint2*>(smem + off)       = make_uint2(h0, h1);
                *reinterpret_cast<uint2*>(smem + SEC + off) = make_uint2(l0, l1);
            }
        }
        CP_WAIT0();
        __syncthreads();
    }

    const int NITER = DIM / GBK;   // 16
    for (int it = 0; it < NITER; it++) {
        const int p    = it & 1;
        const bool pre = (it + 1 < NITER);
        const uint32_t cur = sb + (uint32_t)p * STAGEB;
        const uint32_t nxt = sb + (uint32_t)(p ^ 1) * STAGEB;

        float4 aPre[4];
        if (pre) {
            const int k1 = (it + 1) * GBK;
#pragma unroll
            for (int L = 0; L < 4; L++) {
                int chunk = t + L * 256;
                int r = chunk >> 3, c = chunk & 7;
                int gr = rowBase + r;
                if (gr < N) aPre[L] = *reinterpret_cast<const float4*>(A + (size_t)gr * DIM + k1 + c * 4);
            }
#pragma unroll
            for (int L = 0; L < 2; L++) {
                int chunk = t + L * 256;
                int r = chunk >> 2, c = chunk & 3;
                int gc = colBase + r;
                if (gc < M) {
                    uint32_t off = (uint32_t)((r * APITCH + c * 8) * 2);
                    cp_async16(nxt + 2 * SEC + off, Whi + (size_t)gc * DIM + k1 + c * 8);
                    cp_async16(nxt + 3 * SEC + off, Wlo + (size_t)gc * DIM + k1 + c * 8);
                }
            }
            CP_COMMIT();
        }

#pragma unroll
        for (int kk = 0; kk < GBK; kk += 16) {
            unsigned ah[4][4], al[4][4];
#pragma unroll
            for (int mt = 0; mt < 4; mt++) {
                int row = wm * 64 + mt * 16 + (lg & 1) * 8 + lr;
                int kel = kk + (lg >> 1) * 8;
                unsigned off = (unsigned)((row * APITCH + kel) * 2);
                ldmx4(ah[mt], cur + off);
                ldmx4(al[mt], cur + SEC + off);
            }
            unsigned b[2][4];
#pragma unroll
            for (int nq = 0; nq < 2; nq++) {
                int nrow = wn * 32 + nq * 16 + (lg >> 1) * 8 + lr;
                int kel  = kk + (lg & 1) * 8;
                ldmx4(b[nq], cur + 2 * SEC + (unsigned)((nrow * APITCH + kel) * 2));
            }
#pragma unroll
            for (int mt = 0; mt < 4; mt++)
#pragma unroll
                for (int nt = 0; nt < 4; nt++) {
                    int nq = nt >> 1, h = (nt & 1) * 2;
                    mma_bf16(acc[mt][nt], ah[mt], b[nq][h], b[nq][h + 1]);
                }
#pragma unroll
            for (int mt = 0; mt < 4; mt++)
#pragma unroll
                for (int nt = 0; nt < 4; nt++) {
                    int nq = nt >> 1, h = (nt & 1) * 2;
                    mma_bf16(acc[mt][nt], al[mt], b[nq][h], b[nq][h + 1]);
                }
#pragma unroll
            for (int nq = 0; nq < 2; nq++) {
                int nrow = wn * 32 + nq * 16 + (lg >> 1) * 8 + lr;
                int kel  = kk + (lg & 1) * 8;
                ldmx4(b[nq], cur + 3 * SEC + (unsigned)((nrow * APITCH + kel) * 2));
            }
#pragma unroll
            for (int mt = 0; mt < 4; mt++)
#pragma unroll
                for (int nt = 0; nt < 4; nt++) {
                    int nq = nt >> 1, h = (nt & 1) * 2;
                    mma_bf16(acc[mt][nt], ah[mt], b[nq][h], b[nq][h + 1]);
                }
        }

        if (pre) {
            char* nxtg = smem + (size_t)(p ^ 1) * STAGEB;
#pragma unroll
            for (int L = 0; L < 4; L++) {
                int chunk = t + L * 256;
                int r = chunk >> 3, c = chunk & 7;
                int gr = rowBase + r;
                if (gr < N) {
                    unsigned h0, l0, h1, l1;
                    split2(make_float2(aPre[L].x, aPre[L].y), h0, l0);
                    split2(make_float2(aPre[L].z, aPre[L].w), h1, l1);
                    uint32_t off = (uint32_t)((r * APITCH + c * 4) * 2);
                    *reinterpret_cast<uint2*>(nxtg + off)       = make_uint2(h0, h1);
                    *reinterpret_cast<uint2*>(nxtg + SEC + off) = make_uint2(l0, l1);
                }
            }
            CP_WAIT0();
        }
        __syncthreads();
    }

    // epilogue
    const int group = lane >> 2;
    const int qt    = lane & 3;
#pragma unroll
    for (int mt = 0; mt < 4; mt++) {
#pragma unroll
        for (int nt = 0; nt < 4; nt++) {
            int row0 = rowBase + wm * 64 + mt * 16 + group;
            int col  = colBase + wn * 32 + nt * 8 + qt * 2;
            float b0v = 0.f, b1v = 0.f;
            if (bias) {
                if (col < M)     b0v = bias[col];
                if (col + 1 < M) b1v = bias[col + 1];
            }
            if (row0 < N) {
                if (col + 1 < M) {
                    float2 v = make_float2(acc[mt][nt][0] + b0v, acc[mt][nt][1] + b1v);
                    *reinterpret_cast<float2*>(C + (size_t)row0 * M + col) = v;
                } else if (col < M) {
                    C[(size_t)row0 * M + col] = acc[mt][nt][0] + b0v;
                }
            }
            int row1 = row0 + 8;
            if (row1 < N) {
                if (col + 1 < M) {
                    float2 v = make_float2(acc[mt][nt][2] + b0v, acc[mt][nt][3] + b1v);
                    *reinterpret_cast<float2*>(C + (size_t)row1 * M + col) = v;
                } else if (col < M) {
                    C[(size_t)row1 * M + col] = acc[mt][nt][2] + b0v;
                }
            }
        }
    }
}

// ---------------------------------------------------------------------------
// launch — capture-fork with split join events (R13 schedule, verified best)
// ---------------------------------------------------------------------------
extern "C" void kernel_launch(void* const* d_in, const int* in_sizes, int n_in,
                              void* d_out, int out_size) {
    const float* x  = (const float*)d_in[0];
    const int*   ei = (const int*)  d_in[1];
    const float* W1 = (const float*)d_in[2];
    const float* b1 = (const float*)d_in[3];
    const float* W2 = (const float*)d_in[4];
    const float* b2 = (const float*)d_in[5];
    const float* Wc = (const float*)d_in[6];
    const float* bc = (const float*)d_in[7];
    float* out = (float*)d_out;

    float *hP = nullptr, *aggP = nullptr;
    __nv_bfloat16 *w1hi, *w1lo, *w2hi, *w2lo, *wchi, *wclo;
    cudaGetSymbolAddress((void**)&hP,   g_h);
    cudaGetSymbolAddress((void**)&aggP, g_agg);
    cudaGetSymbolAddress((void**)&w1hi, g_w1hi);
    cudaGetSymbolAddress((void**)&w1lo, g_w1lo);
    cudaGetSymbolAddress((void**)&w2hi, g_w2hi);
    cudaGetSymbolAddress((void**)&w2lo, g_w2lo);
    cudaGetSymbolAddress((void**)&wchi, g_wchi);
    cudaGetSymbolAddress((void**)&wclo, g_wclo);

    cudaFuncSetAttribute(k_gemm_fused, cudaFuncAttributeMaxDynamicSharedMemorySize, SMEMB);

    cudaStream_t s2;
    cudaStreamCreateWithFlags(&s2, cudaStreamNonBlocking);
    cudaEvent_t evFork, evCSR, evW;
    cudaEventCreateWithFlags(&evFork, cudaEventDisableTiming);
    cudaEventCreateWithFlags(&evCSR,  cudaEventDisableTiming);
    cudaEventCreateWithFlags(&evW,    cudaEventDisableTiming);

    const int WT2 = DIM * (DIM / 2);
    const int WC2 = NCLS * (DIM / 2);

    cudaEventRecord(evFork, 0);
    cudaStreamWaitEvent(s2, evFork, 0);

    // ---- side stream: CSR build + norms, then W2/Wc splits ----
    k_zero_cnt<<<(N_NODES + 255) / 256, 256, 0, s2>>>();
    k_count   <<<(N_EDGES + 255) / 256, 256, 0, s2>>>(ei);
    k_norm    <<<(N_NODES + 255) / 256, 256, 0, s2>>>();
    k_scan1   <<<SCAN_BLOCKS, 256, 0, s2>>>();
    k_scan2   <<<1, 256, 0, s2>>>();
    k_scan3   <<<SCAN_BLOCKS, 256, 0, s2>>>();
    k_fill    <<<(N_EDGES + 255) / 256, 256, 0, s2>>>(ei);
    cudaEventRecord(evCSR, s2);
    k_split_w <<<(WT2 + 255) / 256, 256, 0, s2>>>(W2, w2hi, w2lo, DIM);
    k_split_w <<<(WC2 + 255) / 256, 256, 0, s2>>>(Wc, wchi, wclo, NCLS);
    cudaEventRecord(evW, s2);

    dim3 g1((DIM  + GBN - 1) / GBN, (N_NODES + GBM - 1) / GBM);   // (4, 391)
    dim3 g3((NCLS + GBN - 1) / GBN, (N_NODES + GBM - 1) / GBM);   // (1, 391)
    dim3 gg(N_NODES, 2);

    // ---- main stream: layer 1 GEMM (needs only W1 split) ----
    k_split_w   <<<(WT2 + 255) / 256, 256>>>(W1, w1hi, w1lo, DIM);
    k_gemm_fused<<<g1, 256, SMEMB>>>(x, w1hi, w1lo, hP, nullptr, N_NODES, DIM);

    // gather needs only CSR
    cudaStreamWaitEvent(0, evCSR, 0);
    k_gather<<<gg, 64>>>(hP, aggP, b1);

    // layer-2 GEMM additionally needs the weight splits
    cudaStreamWaitEvent(0, evW, 0);
    k_gemm_fused<<<g1, 256, SMEMB>>>(aggP, w2hi, w2lo, hP, nullptr, N_NODES, DIM);
    k_gather<<<gg, 64>>>(hP, aggP, b2);

    // ---- classifier ----
    k_gemm_fused<<<g3, 256, SMEMB>>>(aggP, wchi, wclo, out, bc, N_NODES, NCLS);

    cudaEventDestroy(evFork);
    cudaEventDestroy(evCSR);
    cudaEventDestroy(evW);
    cudaStreamDestroy(s2);
}

// round 17
// speedup vs baseline: 1.0213x; 1.0213x over previous
#include <cuda_runtime.h>
#include <cuda_bf16.h>
#include <cstdint>

#define N_NODES 50000
#define N_EDGES 500000
#define DIM     512
#define NCLS    100

// ---------------------------------------------------------------------------
// scratch (device globals)
// ---------------------------------------------------------------------------
__device__ float g_h  [(size_t)N_NODES * DIM];
__device__ float g_agg[(size_t)N_NODES * DIM];
__device__ float g_norm[N_NODES];
__device__ int   g_cnt [N_NODES];
__device__ int   g_fill[N_NODES];
__device__ int   g_off [N_NODES + 1];
__device__ int   g_csr_src [N_EDGES];
__device__ float g_csr_coef[N_EDGES];

__device__ __nv_bfloat16 g_w1hi[(size_t)DIM * DIM];
__device__ __nv_bfloat16 g_w1lo[(size_t)DIM * DIM];
__device__ __nv_bfloat16 g_w2hi[(size_t)DIM * DIM];
__device__ __nv_bfloat16 g_w2lo[(size_t)DIM * DIM];
__device__ __nv_bfloat16 g_wchi[(size_t)NCLS * DIM];
__device__ __nv_bfloat16 g_wclo[(size_t)NCLS * DIM];

#define SCAN_BLOCKS 196
__device__ int g_bsum[SCAN_BLOCKS];
__device__ int g_bpre[SCAN_BLOCKS];

// ---------------------------------------------------------------------------
// CSR build
// ---------------------------------------------------------------------------
__global__ void k_zero_cnt() {
    int i = blockIdx.x * blockDim.x + threadIdx.x;
    if (i < N_NODES) { g_cnt[i] = 0; g_fill[i] = 0; }
}

__global__ void k_count(const int* __restrict__ ei) {
    int e = blockIdx.x * blockDim.x + threadIdx.x;
    if (e < N_EDGES) atomicAdd(&g_cnt[ei[N_EDGES + e]], 1);
}

__global__ void k_norm() {
    int i = blockIdx.x * blockDim.x + threadIdx.x;
    if (i < N_NODES) g_norm[i] = rsqrtf(1.0f + (float)g_cnt[i]);
}

__device__ __forceinline__ int block_scan256(int v, int t, int* sh, int* tot) {
    int incl = v;
#pragma unroll
    for (int o = 1; o < 32; o <<= 1) {
        int u = __shfl_up_sync(0xffffffffu, incl, o);
        if ((t & 31) >= o) incl += u;
    }
    if ((t & 31) == 31) sh[t >> 5] = incl;
    __syncthreads();
    if (t < 8) {
        int w = sh[t];
        int iw = w;
#pragma unroll
        for (int o = 1; o < 8; o <<= 1) {
            int u = __shfl_up_sync(0xffu, iw, o);
            if (t >= o) iw += u;
        }
        sh[t] = iw - w;
        if (t == 7) *tot = iw;
    }
    __syncthreads();
    return incl + sh[t >> 5];
}

__global__ void __launch_bounds__(256) k_scan1() {
    __shared__ int sh[8]; __shared__ int tot;
    int i = blockIdx.x * 256 + threadIdx.x;
    int v = (i < N_NODES) ? g_cnt[i] : 0;
    block_scan256(v, threadIdx.x, sh, &tot);
    __syncthreads();
    if (threadIdx.x == 0) g_bsum[blockIdx.x] = tot;
}

__global__ void __launch_bounds__(256) k_scan2() {
    __shared__ int sh[8]; __shared__ int tot;
    int t = threadIdx.x;
    int v = (t < SCAN_BLOCKS) ? g_bsum[t] : 0;
    int incl = block_scan256(v, t, sh, &tot);
    if (t < SCAN_BLOCKS) g_bpre[t] = incl - v;
}

__global__ void __launch_bounds__(256) k_scan3() {
    __shared__ int sh[8]; __shared__ int tot;
    int i = blockIdx.x * 256 + threadIdx.x;
    int v = (i < N_NODES) ? g_cnt[i] : 0;
    int incl = block_scan256(v, threadIdx.x, sh, &tot);
    if (i < N_NODES) g_off[i + 1] = incl + g_bpre[blockIdx.x];
    if (i == 0) g_off[0] = 0;
}

__global__ void k_fill(const int* __restrict__ ei) {
    int e = blockIdx.x * blockDim.x + threadIdx.x;
    if (e >= N_EDGES) return;
    int src = ei[e];
    int dst = ei[N_EDGES + e];
    int pos = g_off[dst] + atomicAdd(&g_fill[dst], 1);
    g_csr_src [pos] = src;
    g_csr_coef[pos] = g_norm[src] * g_norm[dst];
}

// ---------------------------------------------------------------------------
// fp32 -> (hi, lo) bf16 split
// ---------------------------------------------------------------------------
__device__ __forceinline__ void split2(float2 a, unsigned& hi2, unsigned& lo2) {
    __nv_bfloat16 hx = __float2bfloat16(a.x);
    __nv_bfloat16 hy = __float2bfloat16(a.y);
    __nv_bfloat16 lx = __float2bfloat16(a.x - __bfloat162float(hx));
    __nv_bfloat16 ly = __float2bfloat16(a.y - __bfloat162float(hy));
    __nv_bfloat162 h = __halves2bfloat162(hx, hy);
    __nv_bfloat162 l = __halves2bfloat162(lx, ly);
    hi2 = *reinterpret_cast<unsigned*>(&h);
    lo2 = *reinterpret_cast<unsigned*>(&l);
}

__global__ void k_split_w(const float* __restrict__ src,
                          __nv_bfloat16* __restrict__ whi,
                          __nv_bfloat16* __restrict__ wlo, int n) {
    int i2 = blockIdx.x * blockDim.x + threadIdx.x;
    int total2 = n * (DIM / 2);
    if (i2 >= total2) return;
    float2 a = reinterpret_cast<const float2*>(src)[i2];
    unsigned hi2, lo2;
    split2(a, hi2, lo2);
    reinterpret_cast<unsigned*>(whi)[i2] = hi2;
    reinterpret_cast<unsigned*>(wlo)[i2] = lo2;
}

// ---------------------------------------------------------------------------
// gather aggregation (fused self-loop + bias + relu)
// feature-tiled via blockIdx.y: columns [y*256, y*256+256); 64 threads/block
// unroll-8 edge loop
// ---------------------------------------------------------------------------
__global__ void __launch_bounds__(64) k_gather(const float* __restrict__ h,
                                               float* __restrict__ agg,
                                               const float* __restrict__ bias) {
    const int node   = blockIdx.x;
    const int colOff = blockIdx.y * 256;
    const int t      = threadIdx.x;
    const int beg    = g_off[node];
    const int end    = g_off[node + 1];
    const float* hc  = h + colOff;

    float4 acc = make_float4(0.f, 0.f, 0.f, 0.f);

    int p = beg;
    for (; p + 8 <= end; p += 8) {
        int   s[8];
        float c[8];
#pragma unroll
        for (int q = 0; q < 8; q++) { s[q] = __ldg(&g_csr_src[p + q]); c[q] = __ldg(&g_csr_coef[p + q]); }
        float4 v[8];
#pragma unroll
        for (int q = 0; q < 8; q++) v[q] = reinterpret_cast<const float4*>(hc + (size_t)s[q] * DIM)[t];
#pragma unroll
        for (int q = 0; q < 8; q++) {
            acc.x = fmaf(c[q], v[q].x, acc.x); acc.y = fmaf(c[q], v[q].y, acc.y);
            acc.z = fmaf(c[q], v[q].z, acc.z); acc.w = fmaf(c[q], v[q].w, acc.w);
        }
    }
    for (; p + 4 <= end; p += 4) {
        int   s0 = __ldg(&g_csr_src[p]),     s1 = __ldg(&g_csr_src[p + 1]);
        int   s2 = __ldg(&g_csr_src[p + 2]), s3 = __ldg(&g_csr_src[p + 3]);
        float c0 = __ldg(&g_csr_coef[p]),     c1 = __ldg(&g_csr_coef[p + 1]);
        float c2 = __ldg(&g_csr_coef[p + 2]), c3 = __ldg(&g_csr_coef[p + 3]);
        float4 v0 = reinterpret_cast<const float4*>(hc + (size_t)s0 * DIM)[t];
        float4 v1 = reinterpret_cast<const float4*>(hc + (size_t)s1 * DIM)[t];
        float4 v2 = reinterpret_cast<const float4*>(hc + (size_t)s2 * DIM)[t];
        float4 v3 = reinterpret_cast<const float4*>(hc + (size_t)s3 * DIM)[t];
        acc.x = fmaf(c0, v0.x, acc.x); acc.y = fmaf(c0, v0.y, acc.y);
        acc.z = fmaf(c0, v0.z, acc.z); acc.w = fmaf(c0, v0.w, acc.w);
        acc.x = fmaf(c1, v1.x, acc.x); acc.y = fmaf(c1, v1.y, acc.y);
        acc.z = fmaf(c1, v1.z, acc.z); acc.w = fmaf(c1, v1.w, acc.w);
        acc.x = fmaf(c2, v2.x, acc.x); acc.y = fmaf(c2, v2.y, acc.y);
        acc.z = fmaf(c2, v2.z, acc.z); acc.w = fmaf(c2, v2.w, acc.w);
        acc.x = fmaf(c3, v3.x, acc.x); acc.y = fmaf(c3, v3.y, acc.y);
        acc.z = fmaf(c3, v3.z, acc.z); acc.w = fmaf(c3, v3.w, acc.w);
    }
    for (; p < end; p++) {
        int   src = g_csr_src[p];
        float c   = g_csr_coef[p];
        float4 v  = reinterpret_cast<const float4*>(hc + (size_t)src * DIM)[t];
        acc.x = fmaf(c, v.x, acc.x);
        acc.y = fmaf(c, v.y, acc.y);
        acc.z = fmaf(c, v.z, acc.z);
        acc.w = fmaf(c, v.w, acc.w);
    }

    float cs = g_norm[node];
    cs = cs * cs;
    float4 hv = reinterpret_cast<const float4*>(hc + (size_t)node * DIM)[t];
    float4 b  = reinterpret_cast<const float4*>(bias + colOff)[t];
    float4 r;
    r.x = fmaxf(fmaf(cs, hv.x, acc.x) + b.x, 0.f);
    r.y = fmaxf(fmaf(cs, hv.y, acc.y) + b.y, 0.f);
    r.z = fmaxf(fmaf(cs, hv.z, acc.z) + b.z, 0.f);
    r.w = fmaxf(fmaf(cs, hv.w, acc.w) + b.w, 0.f);
    reinterpret_cast<float4*>(agg + (size_t)node * DIM + colOff)[t] = r;
}

// ---------------------------------------------------------------------------
// pipelined fused split + bf16 mma.sync GEMM (2-stage, XOR-toggle — verified)
// block 128x128, K-chunk 32, 256 threads = 8 warps as 2(M) x 4(N)
// ---------------------------------------------------------------------------
#define GBM 128
#define GBN 128
#define GBK 32
#define APITCH 40
#define SEC    10240
#define STAGEB (4 * SEC)
#define SMEMB  (2 * STAGEB)

__device__ __forceinline__ void mma_bf16(float* d, const unsigned* a,
                                         unsigned b0, unsigned b1) {
    asm volatile(
        "mma.sync.aligned.m16n8k16.row.col.f32.bf16.bf16.f32 "
        "{%0,%1,%2,%3}, {%4,%5,%6,%7}, {%8,%9}, {%0,%1,%2,%3};"
        : "+f"(d[0]), "+f"(d[1]), "+f"(d[2]), "+f"(d[3])
        : "r"(a[0]), "r"(a[1]), "r"(a[2]), "r"(a[3]), "r"(b0), "r"(b1));
}

__device__ __forceinline__ void ldmx4(unsigned* r, unsigned addr) {
    asm volatile(
        "ldmatrix.sync.aligned.m8n8.x4.shared.b16 {%0,%1,%2,%3}, [%4];"
        : "=r"(r[0]), "=r"(r[1]), "=r"(r[2]), "=r"(r[3])
        : "r"(addr));
}

__device__ __forceinline__ void cp_async16(uint32_t dst, const void* src) {
    asm volatile("cp.async.cg.shared.global [%0], [%1], 16;" :: "r"(dst), "l"(src) : "memory");
}
#define CP_COMMIT() asm volatile("cp.async.commit_group;" ::: "memory")
#define CP_WAIT0()  asm volatile("cp.async.wait_group 0;"  ::: "memory")

__global__ void __launch_bounds__(256) k_gemm_fused(const float* __restrict__ A,
                                                    const __nv_bfloat16* __restrict__ Whi,
                                                    const __nv_bfloat16* __restrict__ Wlo,
                                                    float* __restrict__ C,
                                                    const float* __restrict__ bias,
                                                    int N, int M) {
    extern __shared__ char smem[];
    uint32_t sb;
    asm("{ .reg .u64 t; cvta.to.shared.u64 t, %1; cvt.u32.u64 %0, t; }" : "=r"(sb) : "l"(smem));

    const int t    = threadIdx.x;
    const int lane = t & 31;
    const int warp = t >> 5;
    const int wm   = warp & 1;
    const int wn   = warp >> 1;
    const int rowBase = blockIdx.y * GBM;
    const int colBase = blockIdx.x * GBN;

    const int lg = lane >> 3;
    const int lr = lane & 7;

#pragma unroll
    for (int i = 0; i < SMEMB / 16 / 256; i++)
        reinterpret_cast<uint4*>(smem)[i * 256 + t] = make_uint4(0, 0, 0, 0);
    __syncthreads();

    float acc[4][4][4];
#pragma unroll
    for (int i = 0; i < 4; i++)
#pragma unroll
        for (int j = 0; j < 4; j++)
#pragma unroll
            for (int q = 0; q < 4; q++) acc[i][j][q] = 0.f;

    // ---- prologue: stage 0 ----
    {
        const int k0 = 0;
        float4 aPre[4];
#pragma unroll
        for (int L = 0; L < 4; L++) {
            int chunk = t + L * 256;
            int r = chunk >> 3, c = chunk & 7;
            int gr = rowBase + r;
            if (gr < N) aPre[L] = *reinterpret_cast<const float4*>(A + (size_t)gr * DIM + k0 + c * 4);
        }
#pragma unroll
        for (int L = 0; L < 2; L++) {
            int chunk = t + L * 256;
            int r = chunk >> 2, c = chunk & 3;
            int gc = colBase + r;
            if (gc < M) {
                uint32_t off = (uint32_t)((r * APITCH + c * 8) * 2);
                cp_async16(sb + 2 * SEC + off, Whi + (size_t)gc * DIM + k0 + c * 8);
                cp_async16(sb + 3 * SEC + off, Wlo + (size_t)gc * DIM + k0 + c * 8);
            }
        }
        CP_COMMIT();
#pragma unroll
        for (int L = 0; L < 4; L++) {
            int chunk = t + L * 256;
            int r = chunk >> 3, c = chunk & 7;
            int gr = rowBase + r;
            if (gr < N) {
                unsigned h0, l0, h1, l1;
                split2(make_float2(aPre[L].x, aPre[L].y), h0, l0);
                split2(make_float2(aPre[L].z, aPre[L].w), h1, l1);
                uint32_t off = (uint32_t)((r * APITCH + c * 4) * 2);
                *reinterpret_cast<uint2*>(smem + off)       = make_uint2(h0, h1);
                *reinterpret_cast<uint2*>(smem + SEC + off) = make_uint2(l0, l1);
            }
        }
        CP_WAIT0();
        __syncthreads();
    }

    const int NITER = DIM / GBK;   // 16
    for (int it = 0; it < NITER; it++) {
        const int p    = it & 1;
        const bool pre = (it + 1 < NITER);
        const uint32_t cur = sb + (uint32_t)p * STAGEB;
        const uint32_t nxt = sb + (uint32_t)(p ^ 1) * STAGEB;

        float4 aPre[4];
        if (pre) {
            const int k1 = (it + 1) * GBK;
#pragma unroll
            for (int L = 0; L < 4; L++) {
                int chunk = t + L * 256;
                int r = chunk >> 3, c = chunk & 7;
                int gr = rowBase + r;
                if (gr < N) aPre[L] = *reinterpret_cast<const float4*>(A + (size_t)gr * DIM + k1 + c * 4);
            }
#pragma unroll
            for (int L = 0; L < 2; L++) {
                int chunk = t + L * 256;
                int r = chunk >> 2, c = chunk & 3;
                int gc = colBase + r;
                if (gc < M) {
                    uint32_t off = (uint32_t)((r * APITCH + c * 8) * 2);
                    cp_async16(nxt + 2 * SEC + off, Whi + (size_t)gc * DIM + k1 + c * 8);
                    cp_async16(nxt + 3 * SEC + off, Wlo + (size_t)gc * DIM + k1 + c * 8);
                }
            }
            CP_COMMIT();
        }

#pragma unroll
        for (int kk = 0; kk < GBK; kk += 16) {
            unsigned ah[4][4], al[4][4];
#pragma unroll
            for (int mt = 0; mt < 4; mt++) {
                int row = wm * 64 + mt * 16 + (lg & 1) * 8 + lr;
                int kel = kk + (lg >> 1) * 8;
                unsigned off = (unsigned)((row * APITCH + kel) * 2);
                ldmx4(ah[mt], cur + off);
                ldmx4(al[mt], cur + SEC + off);
            }
            unsigned b[2][4];
#pragma unroll
            for (int nq = 0; nq < 2; nq++) {
                int nrow = wn * 32 + nq * 16 + (lg >> 1) * 8 + lr;
                int kel  = kk + (lg & 1) * 8;
                ldmx4(b[nq], cur + 2 * SEC + (unsigned)((nrow * APITCH + kel) * 2));
            }
#pragma unroll
            for (int mt = 0; mt < 4; mt++)
#pragma unroll
                for (int nt = 0; nt < 4; nt++) {
                    int nq = nt >> 1, h = (nt & 1) * 2;
                    mma_bf16(acc[mt][nt], ah[mt], b[nq][h], b[nq][h + 1]);
                }
#pragma unroll
            for (int mt = 0; mt < 4; mt++)
#pragma unroll
                for (int nt = 0; nt < 4; nt++) {
                    int nq = nt >> 1, h = (nt & 1) * 2;
                    mma_bf16(acc[mt][nt], al[mt], b[nq][h], b[nq][h + 1]);
                }
#pragma unroll
            for (int nq = 0; nq < 2; nq++) {
                int nrow = wn * 32 + nq * 16 + (lg >> 1) * 8 + lr;
                int kel  = kk + (lg & 1) * 8;
                ldmx4(b[nq], cur + 3 * SEC + (unsigned)((nrow * APITCH + kel) * 2));
            }
#pragma unroll
            for (int mt = 0; mt < 4; mt++)
#pragma unroll
                for (int nt = 0; nt < 4; nt++) {
                    int nq = nt >> 1, h = (nt & 1) * 2;
                    mma_bf16(acc[mt][nt], ah[mt], b[nq][h], b[nq][h + 1]);
                }
        }

        if (pre) {
            char* nxtg = smem + (size_t)(p ^ 1) * STAGEB;
#pragma unroll
            for (int L = 0; L < 4; L++) {
                int chunk = t + L * 256;
                int r = chunk >> 3, c = chunk & 7;
                int gr = rowBase + r;
                if (gr < N) {
                    unsigned h0, l0, h1, l1;
                    split2(make_float2(aPre[L].x, aPre[L].y), h0, l0);
                    split2(make_float2(aPre[L].z, aPre[L].w), h1, l1);
                    uint32_t off = (uint32_t)((r * APITCH + c * 4) * 2);
                    *reinterpret_cast<uint2*>(nxtg + off)       = make_uint2(h0, h1);
                    *reinterpret_cast<uint2*>(nxtg + SEC + off) = make_uint2(l0, l1);
                }
            }
            CP_WAIT0();
        }
        __syncthreads();
    }

    // epilogue
    const int group = lane >> 2;
    const int qt    = lane & 3;
#pragma unroll
    for (int mt = 0; mt < 4; mt++) {
#pragma unroll
        for (int nt = 0; nt < 4; nt++) {
            int row0 = rowBase + wm * 64 + mt * 16 + group;
            int col  = colBase + wn * 32 + nt * 8 + qt * 2;
            float b0v = 0.f, b1v = 0.f;
            if (bias) {
                if (col < M)     b0v = bias[col];
                if (col + 1 < M) b1v = bias[col + 1];
            }
            if (row0 < N) {
                if (col + 1 < M) {
                    float2 v = make_float2(acc[mt][nt][0] + b0v, acc[mt][nt][1] + b1v);
                    *reinterpret_cast<float2*>(C + (size_t)row0 * M + col) = v;
                } else if (col < M) {
                    C[(size_t)row0 * M + col] = acc[mt][nt][0] + b0v;
                }
            }
            int row1 = row0 + 8;
            if (row1 < N) {
                if (col + 1 < M) {
                    float2 v = make_float2(acc[mt][nt][2] + b0v, acc[mt][nt][3] + b1v);
                    *reinterpret_cast<float2*>(C + (size_t)row1 * M + col) = v;
                } else if (col < M) {
                    C[(size_t)row1 * M + col] = acc[mt][nt][2] + b0v;
                }
            }
        }
    }
}

// ---------------------------------------------------------------------------
// launch — capture-fork with split join events (verified best schedule)
// ---------------------------------------------------------------------------
extern "C" void kernel_launch(void* const* d_in, const int* in_sizes, int n_in,
                              void* d_out, int out_size) {
    const float* x  = (const float*)d_in[0];
    const int*   ei = (const int*)  d_in[1];
    const float* W1 = (const float*)d_in[2];
    const float* b1 = (const float*)d_in[3];
    const float* W2 = (const float*)d_in[4];
    const float* b2 = (const float*)d_in[5];
    const float* Wc = (const float*)d_in[6];
    const float* bc = (const float*)d_in[7];
    float* out = (float*)d_out;

    float *hP = nullptr, *aggP = nullptr;
    __nv_bfloat16 *w1hi, *w1lo, *w2hi, *w2lo, *wchi, *wclo;
    cudaGetSymbolAddress((void**)&hP,   g_h);
    cudaGetSymbolAddress((void**)&aggP, g_agg);
    cudaGetSymbolAddress((void**)&w1hi, g_w1hi);
    cudaGetSymbolAddress((void**)&w1lo, g_w1lo);
    cudaGetSymbolAddress((void**)&w2hi, g_w2hi);
    cudaGetSymbolAddress((void**)&w2lo, g_w2lo);
    cudaGetSymbolAddress((void**)&wchi, g_wchi);
    cudaGetSymbolAddress((void**)&wclo, g_wclo);

    cudaFuncSetAttribute(k_gemm_fused, cudaFuncAttributeMaxDynamicSharedMemorySize, SMEMB);

    cudaStream_t s2;
    cudaStreamCreateWithFlags(&s2, cudaStreamNonBlocking);
    cudaEvent_t evFork, evCSR, evW;
    cudaEventCreateWithFlags(&evFork, cudaEventDisableTiming);
    cudaEventCreateWithFlags(&evCSR,  cudaEventDisableTiming);
    cudaEventCreateWithFlags(&evW,    cudaEventDisableTiming);

    const int WT2 = DIM * (DIM / 2);
    const int WC2 = NCLS * (DIM / 2);

    cudaEventRecord(evFork, 0);
    cudaStreamWaitEvent(s2, evFork, 0);

    // ---- side stream: CSR build + norms, then W2/Wc splits ----
    k_zero_cnt<<<(N_NODES + 255) / 256, 256, 0, s2>>>();
    k_count   <<<(N_EDGES + 255) / 256, 256, 0, s2>>>(ei);
    k_norm    <<<(N_NODES + 255) / 256, 256, 0, s2>>>();
    k_scan1   <<<SCAN_BLOCKS, 256, 0, s2>>>();
    k_scan2   <<<1, 256, 0, s2>>>();
    k_scan3   <<<SCAN_BLOCKS, 256, 0, s2>>>();
    k_fill    <<<(N_EDGES + 255) / 256, 256, 0, s2>>>(ei);
    cudaEventRecord(evCSR, s2);
    k_split_w <<<(WT2 + 255) / 256, 256, 0, s2>>>(W2, w2hi, w2lo, DIM);
    k_split_w <<<(WC2 + 255) / 256, 256, 0, s2>>>(Wc, wchi, wclo, NCLS);
    cudaEventRecord(evW, s2);

    dim3 g1((DIM  + GBN - 1) / GBN, (N_NODES + GBM - 1) / GBM);   // (4, 391)
    dim3 g3((NCLS + GBN - 1) / GBN, (N_NODES + GBM - 1) / GBM);   // (1, 391)
    dim3 gg(N_NODES, 2);

    // ---- main stream: layer 1 GEMM (needs only W1 split) ----
    k_split_w   <<<(WT2 + 255) / 256, 256>>>(W1, w1hi, w1lo, DIM);
    k_gemm_fused<<<g1, 256, SMEMB>>>(x, w1hi, w1lo, hP, nullptr, N_NODES, DIM);

    // gather needs only CSR
    cudaStreamWaitEvent(0, evCSR, 0);
    k_gather<<<gg, 64>>>(hP, aggP, b1);

    // layer-2 GEMM additionally needs the weight splits
    cudaStreamWaitEvent(0, evW, 0);
    k_gemm_fused<<<g1, 256, SMEMB>>>(aggP, w2hi, w2lo, hP, nullptr, N_NODES, DIM);
    k_gather<<<gg, 64>>>(hP, aggP, b2);

    // ---- classifier ----
    k_gemm_fused<<<g3, 256, SMEMB>>>(aggP, wchi, wclo, out, bc, N_NODES, NCLS);

    cudaEventDestroy(evFork);
    cudaEventDestroy(evCSR);
    cudaEventDestroy(evW);
    cudaStreamDestroy(s2);
}